// round 9
// baseline (speedup 1.0000x reference)
#include <cuda_runtime.h>
#include <cuda_bf16.h>
#include <cstdint>

// Problem constants (fixed by the reference): N=100000, M=8, K=256, D=64
#define PQ_N 100000
#define PQ_M 8
#define PQ_K 256
#define PQ_D 64
#define TILE_M 128
#define THREADS 128
#define WINDOW 0.25f
#define FLT_BIG 3.402823466e38f

// smem (floats): A frags 8192 (32KB) | B frags 16384 (64KB) | csq 256 (1KB)
#define SM_AF  0
#define SM_BF  8192
#define SM_CSQ (8192 + 16384)
#define SM_FLOATS (SM_CSQ + 256)

__device__ __forceinline__ uint32_t f2tf32(float v) {
    uint32_t t;
    asm("cvt.rna.tf32.f32 %0, %1;" : "=r"(t) : "f"(v));
    return t;
}

__device__ __forceinline__ void mma8(float* d, const uint4& a, const uint2& b) {
    asm volatile(
        "mma.sync.aligned.m16n8k8.row.col.f32.tf32.tf32.f32 "
        "{%0,%1,%2,%3}, {%4,%5,%6,%7}, {%8,%9}, {%0,%1,%2,%3};"
        : "+f"(d[0]), "+f"(d[1]), "+f"(d[2]), "+f"(d[3])
        : "r"(a.x), "r"(a.y), "r"(a.z), "r"(a.w), "r"(b.x), "r"(b.y));
}

// NEON/LLVM-emulated sum of squares (frozen: matches reference c_sq / x_sq)
__device__ __forceinline__ float neon_sumsq64(const float* v) {
    float a0[4] = {0.f,0.f,0.f,0.f}, a1[4] = {0.f,0.f,0.f,0.f};
    #pragma unroll
    for (int i = 0; i < 8; ++i) {
        #pragma unroll
        for (int l = 0; l < 4; ++l) {
            a0[l] = __fadd_rn(a0[l], __fmul_rn(v[8*i+l],   v[8*i+l]));
            a1[l] = __fadd_rn(a1[l], __fmul_rn(v[8*i+4+l], v[8*i+4+l]));
        }
    }
    float s0 = __fadd_rn(a0[0],a1[0]), s1 = __fadd_rn(a0[1],a1[1]);
    float s2 = __fadd_rn(a0[2],a1[2]), s3 = __fadd_rn(a0[3],a1[3]);
    return __fadd_rn(__fadd_rn(s0,s1), __fadd_rn(s2,s3));
}

// FROZEN H1 exact dist (bit-identical to reference): dot = rn-mul + rn-add
// chain over d ascending; dist = fl(fl(xsq - fl(2*dot)) + csq).
__device__ __forceinline__ float h1_dist(const float* xw, float xsq,
                                         const float* cg, float csqk) {
    float ea = 0.f;
    #pragma unroll 4
    for (int d = 0; d < 64; ++d)
        ea = __fadd_rn(ea, __fmul_rn(xw[d], cg[d]));
    return __fadd_rn(__fsub_rn(xsq, __fmul_rn(2.0f, ea)), csqk);
}

extern "C" __global__ void __launch_bounds__(THREADS, 2)
pq_mma_kernel(const float* __restrict__ x,
              const float* __restrict__ cb,
              float* __restrict__ qout,
              float* __restrict__ idf,
              long long* __restrict__ idl,
              int id_mode)
{
    extern __shared__ float smem[];
    uint32_t* Af = reinterpret_cast<uint32_t*>(smem + SM_AF);
    uint32_t* Bf = reinterpret_cast<uint32_t*>(smem + SM_BF);
    float*   csq = smem + SM_CSQ;

    const int tid  = threadIdx.x;
    const int w    = tid >> 5;
    const int lane = tid & 31;
    const int g    = lane >> 2;
    const int tq   = lane & 3;
    const int m    = blockIdx.y;
    const int n0   = blockIdx.x * TILE_M;
    const float* cbm = cb + (size_t)m * PQ_K * PQ_D;

    // ---- stage A: x row tid -> tf32 fragments (zeros for OOB rows) ----
    {
        const int n = n0 + tid;
        float xw[64];
        if (n < PQ_N) {
            const float4* gx = reinterpret_cast<const float4*>(
                x + (size_t)n * (PQ_M * PQ_D) + (size_t)m * PQ_D);
            #pragma unroll
            for (int d4 = 0; d4 < 16; ++d4) {
                float4 v = gx[d4];
                xw[d4*4+0]=v.x; xw[d4*4+1]=v.y; xw[d4*4+2]=v.z; xw[d4*4+3]=v.w;
            }
        } else {
            #pragma unroll
            for (int d = 0; d < 64; ++d) xw[d] = 0.f;
        }
        const int rt = tid >> 4, gg = tid & 7, h8 = (tid >> 3) & 1;
        #pragma unroll
        for (int d = 0; d < 64; ++d) {
            int s = d >> 3, u = d & 7, t = u & 3;
            int reg = ((u >= 4) ? 2 : 0) + h8;
            Af[(((rt*8 + s)*32 + gg*4 + t) << 2) + reg] = f2tf32(xw[d]);
        }
    }

    // ---- stage B: cb rows tid, tid+128 -> tf32 fragments; exact NEON csq ----
    #pragma unroll
    for (int r = 0; r < 2; ++r) {
        const int k = tid + r * 128;
        const float4* src = reinterpret_cast<const float4*>(cbm + (size_t)k * PQ_D);
        float cw[64];
        #pragma unroll
        for (int d4 = 0; d4 < 16; ++d4) {
            float4 v = src[d4];
            cw[d4*4+0]=v.x; cw[d4*4+1]=v.y; cw[d4*4+2]=v.z; cw[d4*4+3]=v.w;
        }
        csq[k] = neon_sumsq64(cw);
        const int ct = k >> 3, c = k & 7;
        #pragma unroll
        for (int d = 0; d < 64; ++d) {
            int s = d >> 3, u = d & 7, t = u & 3;
            int reg = (u >= 4) ? 1 : 0;
            Bf[(((ct*8 + s)*32 + c*4 + t) << 1) + reg] = f2tf32(cw[d]);
        }
    }
    __syncthreads();

    // per-row candidate state: 4 rows/thread (ri = r01*2 + h)
    float M0[4], M1[4], M2[4], M3[4];
    int   I0[4], I1[4], I2[4], I3[4], OV[4];
    #pragma unroll
    for (int i = 0; i < 4; ++i) {
        M0[i]=M1[i]=M2[i]=M3[i]=FLT_BIG;
        I0[i]=I1[i]=I2[i]=I3[i]=0; OV[i]=0;
    }

    const uint4* Af4 = reinterpret_cast<const uint4*>(Af);
    const uint2* Bf2 = reinterpret_cast<const uint2*>(Bf);

    // ---- main: 4 chunks of 8 col-tiles (64 codewords) ----
    #pragma unroll 1
    for (int cc = 0; cc < 4; ++cc) {
        float acc[2][8][4];
        #pragma unroll
        for (int a = 0; a < 2; ++a)
            #pragma unroll
            for (int b = 0; b < 8; ++b)
                #pragma unroll
                for (int q = 0; q < 4; ++q) acc[a][b][q] = 0.f;

        #pragma unroll
        for (int s = 0; s < 8; ++s) {
            uint4 a0 = Af4[((2*w)  *8 + s)*32 + lane];
            uint4 a1 = Af4[((2*w+1)*8 + s)*32 + lane];
            #pragma unroll
            for (int ctl = 0; ctl < 8; ++ctl) {
                uint2 b = Bf2[(((cc*8 + ctl)*8 + s)*32 + lane)];
                mma8(acc[0][ctl], a0, b);
                mma8(acc[1][ctl], a1, b);
            }
        }

        // scores: s = csq[k] - 2*cross  (exact csq, tf32 cross)
        #pragma unroll
        for (int r01 = 0; r01 < 2; ++r01) {
            #pragma unroll
            for (int ctl = 0; ctl < 8; ++ctl) {
                #pragma unroll
                for (int q = 0; q < 4; ++q) {
                    const int ri = r01*2 + (q >> 1);
                    const int k  = (cc*8 + ctl)*8 + tq*2 + (q & 1);
                    float s = fmaf(-2.0f, acc[r01][ctl][q], csq[k]);
                    if (s < M3[ri]) {
                        float ev = M3[ri];
                        if (s < M0[ri]) {
                            M3[ri]=M2[ri]; I3[ri]=I2[ri];
                            M2[ri]=M1[ri]; I2[ri]=I1[ri];
                            M1[ri]=M0[ri]; I1[ri]=I0[ri];
                            M0[ri]=s;      I0[ri]=k;
                        } else if (s < M1[ri]) {
                            M3[ri]=M2[ri]; I3[ri]=I2[ri];
                            M2[ri]=M1[ri]; I2[ri]=I1[ri];
                            M1[ri]=s;      I1[ri]=k;
                        } else if (s < M2[ri]) {
                            M3[ri]=M2[ri]; I3[ri]=I2[ri];
                            M2[ri]=s;      I2[ri]=k;
                        } else { M3[ri]=s; I3[ri]=k; }
                        OV[ri] |= (ev < M0[ri] + WINDOW);
                    } else {
                        OV[ri] |= (s < M0[ri] + WINDOW);
                    }
                }
            }
        }
    }

    // ---- finalize 4 rows (all shfls unconditional: converged warp) ----
    #pragma unroll 1
    for (int ri = 0; ri < 4; ++ri) {
        const int row = w*32 + (ri >> 1)*16 + (ri & 1)*8 + g;
        const int n   = n0 + row;

        // quad reduce global approx min (tie -> lower k)
        float gm = M0[ri]; int gk = I0[ri];
        #pragma unroll
        for (int off = 1; off <= 2; off <<= 1) {
            float om = __shfl_xor_sync(0xffffffffu, gm, off);
            int   ok = __shfl_xor_sync(0xffffffffu, gk, off);
            if (om < gm || (om == gm && ok < gk)) { gm = om; gk = ok; }
        }
        const float thr = gm + WINDOW;
        int v = (M0[ri]<thr) + (M1[ri]<thr) + (M2[ri]<thr) + (M3[ri]<thr);
        v += __shfl_xor_sync(0xffffffffu, v, 1);
        v += __shfl_xor_sync(0xffffffffu, v, 2);
        int o = OV[ri];
        o |= __shfl_xor_sync(0xffffffffu, o, 1);
        o |= __shfl_xor_sync(0xffffffffu, o, 2);

        const bool refine = (n < PQ_N) && (v >= 2 || o);

        // per-thread exact best over its candidates (guarded, no shfl inside)
        float bd = FLT_BIG; int bk = 1 << 30;
        if (refine) {
            float xw[64];
            const float4* gx = reinterpret_cast<const float4*>(
                x + (size_t)n * (PQ_M * PQ_D) + (size_t)m * PQ_D);
            #pragma unroll
            for (int d4 = 0; d4 < 16; ++d4) {
                float4 vv = gx[d4];
                xw[d4*4+0]=vv.x; xw[d4*4+1]=vv.y; xw[d4*4+2]=vv.z; xw[d4*4+3]=vv.w;
            }
            const float xsq = neon_sumsq64(xw);
            if (OV[ri]) {
                // overflow fallback: exact scan of ALL 64 ks owned by this thread
                for (int ct = 0; ct < 32; ++ct) {
                    #pragma unroll
                    for (int j = 0; j < 2; ++j) {
                        const int k = ct*8 + tq*2 + j;
                        float dd = h1_dist(xw, xsq, cbm + (size_t)k * PQ_D, csq[k]);
                        if (dd < bd || (dd == bd && k < bk)) { bd = dd; bk = k; }
                    }
                }
            } else {
                float mm[4] = {M0[ri], M1[ri], M2[ri], M3[ri]};
                int   ii[4] = {I0[ri], I1[ri], I2[ri], I3[ri]};
                #pragma unroll
                for (int c = 0; c < 4; ++c) {
                    if (mm[c] < thr) {
                        const int k = ii[c];
                        float dd = h1_dist(xw, xsq, cbm + (size_t)k * PQ_D, csq[k]);
                        if (dd < bd || (dd == bd && k < bk)) { bd = dd; bk = k; }
                    }
                }
            }
        }
        // quad reduce exact best (unconditional shfl)
        #pragma unroll
        for (int off = 1; off <= 2; off <<= 1) {
            float ob = __shfl_xor_sync(0xffffffffu, bd, off);
            int   ok = __shfl_xor_sync(0xffffffffu, bk, off);
            if (ob < bd || (ob == bd && ok < bk)) { bd = ob; bk = ok; }
        }

        const int ibest = (v >= 2 || o) ? bk : gk;

        if (n < PQ_N && tq == 0) {
            const float4* cg4 = reinterpret_cast<const float4*>(
                cbm + (size_t)ibest * PQ_D);
            float4* qrow = reinterpret_cast<float4*>(
                qout + (size_t)n * (PQ_M * PQ_D) + (size_t)m * PQ_D);
            #pragma unroll
            for (int d4 = 0; d4 < 16; ++d4) qrow[d4] = cg4[d4];
            if (id_mode == 1)      idf[(size_t)m * PQ_N + n] = (float)ibest;
            else if (id_mode == 2) idl[(size_t)m * PQ_N + n] = (long long)ibest;
        }
    }
}

extern "C" void kernel_launch(void* const* d_in, const int* in_sizes, int n_in,
                              void* d_out, int out_size) {
    const float* x  = (const float*)d_in[0];   // (N, 512) f32
    const float* cb = (const float*)d_in[1];   // (8, 256, 64) f32

    float* out = (float*)d_out;
    const long long QN  = (long long)PQ_N * PQ_M * PQ_D;  // 51,200,000
    const long long IDN = (long long)PQ_M * PQ_N;         // 800,000

    int id_mode = 0;
    float* idf = nullptr;
    long long* idl = nullptr;
    long long osz = (long long)out_size;
    if (osz >= QN + 2 * IDN) {
        id_mode = 2;
        idl = reinterpret_cast<long long*>(out + QN);
    } else if (osz >= QN + IDN) {
        id_mode = 1;
        idf = out + QN;
    }

    const int smem_bytes = SM_FLOATS * sizeof(float);  // ~97KB
    cudaFuncSetAttribute(pq_mma_kernel,
                         cudaFuncAttributeMaxDynamicSharedMemorySize, smem_bytes);

    dim3 grid((PQ_N + TILE_M - 1) / TILE_M, PQ_M);
    pq_mma_kernel<<<grid, THREADS, smem_bytes>>>(x, cb, out, idf, idl, id_mode);
}

// round 10
// speedup vs baseline: 1.6654x; 1.6654x over previous
#include <cuda_runtime.h>
#include <cuda_bf16.h>
#include <cstdint>

// Problem constants (fixed by the reference): N=100000, M=8, K=256, D=64
#define PQ_N 100000
#define PQ_M 8
#define PQ_K 256
#define PQ_D 64
#define TILE_M 128
#define THREADS 256
#define WINDOW 0.25f
#define FLT_BIG 3.402823466e38f

// smem (floats): A frags 8192 (32KB) | B frags 16384 (64KB) | csq 256 (1KB)
#define SM_AF  0
#define SM_BF  8192
#define SM_CSQ (8192 + 16384)
#define SM_FLOATS (SM_CSQ + 256)

__device__ __forceinline__ uint32_t f2tf32(float v) {
    uint32_t t;
    asm("cvt.rna.tf32.f32 %0, %1;" : "=r"(t) : "f"(v));
    return t;
}

__device__ __forceinline__ void mma8(float* d, const uint4& a, const uint2& b) {
    asm volatile(
        "mma.sync.aligned.m16n8k8.row.col.f32.tf32.tf32.f32 "
        "{%0,%1,%2,%3}, {%4,%5,%6,%7}, {%8,%9}, {%0,%1,%2,%3};"
        : "+f"(d[0]), "+f"(d[1]), "+f"(d[2]), "+f"(d[3])
        : "r"(a.x), "r"(a.y), "r"(a.z), "r"(a.w), "r"(b.x), "r"(b.y));
}

// NEON/LLVM-emulated sum of squares (frozen: matches reference c_sq / x_sq)
__device__ __forceinline__ float neon_sumsq64(const float* v) {
    float a0[4] = {0.f,0.f,0.f,0.f}, a1[4] = {0.f,0.f,0.f,0.f};
    #pragma unroll
    for (int i = 0; i < 8; ++i) {
        #pragma unroll
        for (int l = 0; l < 4; ++l) {
            a0[l] = __fadd_rn(a0[l], __fmul_rn(v[8*i+l],   v[8*i+l]));
            a1[l] = __fadd_rn(a1[l], __fmul_rn(v[8*i+4+l], v[8*i+4+l]));
        }
    }
    float s0 = __fadd_rn(a0[0],a1[0]), s1 = __fadd_rn(a0[1],a1[1]);
    float s2 = __fadd_rn(a0[2],a1[2]), s3 = __fadd_rn(a0[3],a1[3]);
    return __fadd_rn(__fadd_rn(s0,s1), __fadd_rn(s2,s3));
}

// FROZEN H1 exact dist (bit-identical to reference): dot = rn-mul + rn-add
// chain over d ascending; dist = fl(fl(xsq - fl(2*dot)) + csq).
__device__ __forceinline__ float h1_dist(const float* __restrict__ xg, float xsq,
                                         const float* __restrict__ cg, float csqk) {
    float ea = 0.f;
    #pragma unroll 8
    for (int d = 0; d < 64; ++d)
        ea = __fadd_rn(ea, __fmul_rn(xg[d], cg[d]));
    return __fadd_rn(__fsub_rn(xsq, __fmul_rn(2.0f, ea)), csqk);
}

// branchless-ish running (min, argmin) + second-min value (no index)
__device__ __forceinline__ void upd(float& m1, float& m2, int& i1, float s, int k) {
    if (s < m1) { m2 = m1; m1 = s; i1 = k; }
    else        { m2 = fminf(m2, s); }
}

extern "C" __global__ void __launch_bounds__(THREADS, 2)
pq_mma_kernel(const float* __restrict__ x,
              const float* __restrict__ cb,
              float* __restrict__ qout,
              float* __restrict__ idf,
              long long* __restrict__ idl,
              int id_mode)
{
    extern __shared__ float smem[];
    uint32_t* Af = reinterpret_cast<uint32_t*>(smem + SM_AF);
    uint32_t* Bf = reinterpret_cast<uint32_t*>(smem + SM_BF);
    float*   csq = smem + SM_CSQ;

    const int tid  = threadIdx.x;
    const int w    = tid >> 5;
    const int lane = tid & 31;
    const int g    = lane >> 2;
    const int tq   = lane & 3;
    const int m    = blockIdx.y;
    const int n0   = blockIdx.x * TILE_M;
    const float* cbm = cb + (size_t)m * PQ_K * PQ_D;

    // ---- stage A: tid<128 stages x row tid (streamed, no big arrays) ----
    if (tid < 128) {
        const int n = n0 + tid;
        const float4* gx = (n < PQ_N)
            ? reinterpret_cast<const float4*>(
                  x + (size_t)n * (PQ_M * PQ_D) + (size_t)m * PQ_D)
            : nullptr;
        const int rt = tid >> 4, gg = tid & 7, h8 = (tid >> 3) & 1;
        #pragma unroll
        for (int s = 0; s < 8; ++s) {
            float4 v0, v1;
            if (gx) { v0 = gx[2*s]; v1 = gx[2*s+1]; }
            else    { v0 = make_float4(0,0,0,0); v1 = v0; }
            uint32_t* base = Af + (((rt*8 + s)*32 + gg*4) << 2);
            // j = 0..3 -> reg = 0 + h8 ; j = 4..7 -> reg = 2 + h8
            base[(0<<2) + 0 + h8] = f2tf32(v0.x);
            base[(1<<2) + 0 + h8] = f2tf32(v0.y);
            base[(2<<2) + 0 + h8] = f2tf32(v0.z);
            base[(3<<2) + 0 + h8] = f2tf32(v0.w);
            base[(0<<2) + 2 + h8] = f2tf32(v1.x);
            base[(1<<2) + 2 + h8] = f2tf32(v1.y);
            base[(2<<2) + 2 + h8] = f2tf32(v1.z);
            base[(3<<2) + 2 + h8] = f2tf32(v1.w);
        }
    }

    // ---- stage B: all 256 threads stage cb row k=tid; exact NEON csq ----
    {
        const int k = tid;
        const float4* src = reinterpret_cast<const float4*>(cbm + (size_t)k * PQ_D);
        const int ct = k >> 3, c = k & 7;
        float a0[4] = {0,0,0,0}, a1[4] = {0,0,0,0};
        #pragma unroll
        for (int s = 0; s < 8; ++s) {
            float4 v0 = src[2*s], v1 = src[2*s+1];
            // NEON reduce update (order identical to neon_sumsq64)
            a0[0] = __fadd_rn(a0[0], __fmul_rn(v0.x, v0.x));
            a0[1] = __fadd_rn(a0[1], __fmul_rn(v0.y, v0.y));
            a0[2] = __fadd_rn(a0[2], __fmul_rn(v0.z, v0.z));
            a0[3] = __fadd_rn(a0[3], __fmul_rn(v0.w, v0.w));
            a1[0] = __fadd_rn(a1[0], __fmul_rn(v1.x, v1.x));
            a1[1] = __fadd_rn(a1[1], __fmul_rn(v1.y, v1.y));
            a1[2] = __fadd_rn(a1[2], __fmul_rn(v1.z, v1.z));
            a1[3] = __fadd_rn(a1[3], __fmul_rn(v1.w, v1.w));
            uint32_t* base = Bf + (((ct*8 + s)*32 + c*4) << 1);
            base[(0<<1) + 0] = f2tf32(v0.x);
            base[(1<<1) + 0] = f2tf32(v0.y);
            base[(2<<1) + 0] = f2tf32(v0.z);
            base[(3<<1) + 0] = f2tf32(v0.w);
            base[(0<<1) + 1] = f2tf32(v1.x);
            base[(1<<1) + 1] = f2tf32(v1.y);
            base[(2<<1) + 1] = f2tf32(v1.z);
            base[(3<<1) + 1] = f2tf32(v1.w);
        }
        float s0 = __fadd_rn(a0[0],a1[0]), s1 = __fadd_rn(a0[1],a1[1]);
        float s2 = __fadd_rn(a0[2],a1[2]), s3 = __fadd_rn(a0[3],a1[3]);
        csq[k] = __fadd_rn(__fadd_rn(s0,s1), __fadd_rn(s2,s3));
    }
    __syncthreads();

    // ---- preload this warp's A fragments (row-tile = w): 32 regs ----
    const uint4* Af4 = reinterpret_cast<const uint4*>(Af);
    const uint2* Bf2 = reinterpret_cast<const uint2*>(Bf);
    uint4 afr[8];
    #pragma unroll
    for (int s = 0; s < 8; ++s) afr[s] = Af4[(w*8 + s)*32 + lane];

    // per-row state: 2 rows/thread (ra: row w*16+g, rb: row w*16+8+g)
    float m1a = FLT_BIG, m2a = FLT_BIG, m1b = FLT_BIG, m2b = FLT_BIG;
    int   i1a = 0, i1b = 0;

    // ---- main: 32 col-tiles in pairs (2 independent mma chains) ----
    #pragma unroll 2
    for (int ctl = 0; ctl < 32; ctl += 2) {
        float acc0[4] = {0,0,0,0}, acc1[4] = {0,0,0,0};
        #pragma unroll
        for (int s = 0; s < 8; ++s) {
            uint2 b0 = Bf2[((ctl    )*8 + s)*32 + lane];
            uint2 b1 = Bf2[((ctl + 1)*8 + s)*32 + lane];
            mma8(acc0, afr[s], b0);
            mma8(acc1, afr[s], b1);
        }
        // scores s = csq[k] - 2*cross (exact csq, tf32 cross); ascending k
        const int k0 = ctl*8 + tq*2;
        upd(m1a, m2a, i1a, fmaf(-2.0f, acc0[0], csq[k0    ]), k0);
        upd(m1a, m2a, i1a, fmaf(-2.0f, acc0[1], csq[k0 + 1]), k0 + 1);
        upd(m1b, m2b, i1b, fmaf(-2.0f, acc0[2], csq[k0    ]), k0);
        upd(m1b, m2b, i1b, fmaf(-2.0f, acc0[3], csq[k0 + 1]), k0 + 1);
        const int k1 = k0 + 8;
        upd(m1a, m2a, i1a, fmaf(-2.0f, acc1[0], csq[k1    ]), k1);
        upd(m1a, m2a, i1a, fmaf(-2.0f, acc1[1], csq[k1 + 1]), k1 + 1);
        upd(m1b, m2b, i1b, fmaf(-2.0f, acc1[2], csq[k1    ]), k1);
        upd(m1b, m2b, i1b, fmaf(-2.0f, acc1[3], csq[k1 + 1]), k1 + 1);
    }

    // ---- finalize 2 rows (all shfls unconditional: converged warp) ----
    #pragma unroll 1
    for (int ri = 0; ri < 2; ++ri) {
        const float m1 = ri ? m1b : m1a;
        const float m2 = ri ? m2b : m2a;
        const int   i1 = ri ? i1b : i1a;
        const int  row = w*16 + ri*8 + g;
        const int    n = n0 + row;

        // quad reduce approx min (tie -> lower k)
        float gm = m1; int gk = i1;
        #pragma unroll
        for (int off = 1; off <= 2; off <<= 1) {
            float om = __shfl_xor_sync(0xffffffffu, gm, off);
            int   ok = __shfl_xor_sync(0xffffffffu, gk, off);
            if (om < gm || (om == gm && ok < gk)) { gm = om; gk = ok; }
        }
        const float thr = gm + WINDOW;

        int nv = (m1 < thr);
        nv += __shfl_xor_sync(0xffffffffu, nv, 1);
        nv += __shfl_xor_sync(0xffffffffu, nv, 2);
        int o = (m2 < thr);
        o |= __shfl_xor_sync(0xffffffffu, o, 1);
        o |= __shfl_xor_sync(0xffffffffu, o, 2);

        const bool need = (nv >= 2) || o;
        const bool refine = (n < PQ_N) && need;

        float bd = FLT_BIG; int bk = 1 << 30;
        if (refine) {
            const float* xg = x + (size_t)n * (PQ_M * PQ_D) + (size_t)m * PQ_D;
            const float xsq = neon_sumsq64(xg);
            if (m2 < thr) {
                // hidden candidates possible: exact scan this thread's 64 ks
                for (int ct = 0; ct < 32; ++ct) {
                    #pragma unroll
                    for (int j = 0; j < 2; ++j) {
                        const int k = ct*8 + tq*2 + j;
                        float dd = h1_dist(xg, xsq, cbm + (size_t)k * PQ_D, csq[k]);
                        if (dd < bd || (dd == bd && k < bk)) { bd = dd; bk = k; }
                    }
                }
            } else if (m1 < thr) {
                bd = h1_dist(xg, xsq, cbm + (size_t)i1 * PQ_D, csq[i1]);
                bk = i1;
            }
        }
        // quad reduce exact best (tie -> lower k)
        #pragma unroll
        for (int off = 1; off <= 2; off <<= 1) {
            float ob = __shfl_xor_sync(0xffffffffu, bd, off);
            int   ok = __shfl_xor_sync(0xffffffffu, bk, off);
            if (ob < bd || (ob == bd && ok < bk)) { bd = ob; bk = ok; }
        }

        const int ibest = need ? bk : gk;

        if (n < PQ_N && tq == 0) {
            const float4* cg4 = reinterpret_cast<const float4*>(
                cbm + (size_t)ibest * PQ_D);
            float4* qrow = reinterpret_cast<float4*>(
                qout + (size_t)n * (PQ_M * PQ_D) + (size_t)m * PQ_D);
            #pragma unroll
            for (int d4 = 0; d4 < 16; ++d4) qrow[d4] = cg4[d4];
            if (id_mode == 1)      idf[(size_t)m * PQ_N + n] = (float)ibest;
            else if (id_mode == 2) idl[(size_t)m * PQ_N + n] = (long long)ibest;
        }
    }
}

extern "C" void kernel_launch(void* const* d_in, const int* in_sizes, int n_in,
                              void* d_out, int out_size) {
    const float* x  = (const float*)d_in[0];   // (N, 512) f32
    const float* cb = (const float*)d_in[1];   // (8, 256, 64) f32

    float* out = (float*)d_out;
    const long long QN  = (long long)PQ_N * PQ_M * PQ_D;  // 51,200,000
    const long long IDN = (long long)PQ_M * PQ_N;         // 800,000

    int id_mode = 0;
    float* idf = nullptr;
    long long* idl = nullptr;
    long long osz = (long long)out_size;
    if (osz >= QN + 2 * IDN) {
        id_mode = 2;
        idl = reinterpret_cast<long long*>(out + QN);
    } else if (osz >= QN + IDN) {
        id_mode = 1;
        idf = out + QN;
    }

    const int smem_bytes = SM_FLOATS * sizeof(float);  // ~97KB
    cudaFuncSetAttribute(pq_mma_kernel,
                         cudaFuncAttributeMaxDynamicSharedMemorySize, smem_bytes);

    dim3 grid((PQ_N + TILE_M - 1) / TILE_M, PQ_M);
    pq_mma_kernel<<<grid, THREADS, smem_bytes>>>(x, cb, out, idf, idl, id_mode);
}

// round 11
// speedup vs baseline: 1.6659x; 1.0003x over previous
#include <cuda_runtime.h>
#include <cuda_bf16.h>
#include <cstdint>

// Problem constants (fixed by the reference): N=100000, M=8, K=256, D=64
#define PQ_N 100000
#define PQ_M 8
#define PQ_K 256
#define PQ_D 64
#define TILE_M 128
#define THREADS 256
#define WINDOW 0.25f
#define FLT_BIG 3.402823466e38f

// smem (floats): A frags 8192 (32KB) | B frags 16384 (64KB) | csq 256 (1KB)
#define SM_AF  0
#define SM_BF  8192
#define SM_CSQ (8192 + 16384)
#define SM_FLOATS (SM_CSQ + 256)

__device__ __forceinline__ uint32_t f2tf32(float v) {
    uint32_t t;
    asm("cvt.rna.tf32.f32 %0, %1;" : "=r"(t) : "f"(v));
    return t;
}

__device__ __forceinline__ void mma8(float* d, const uint4& a, const uint2& b) {
    asm volatile(
        "mma.sync.aligned.m16n8k8.row.col.f32.tf32.tf32.f32 "
        "{%0,%1,%2,%3}, {%4,%5,%6,%7}, {%8,%9}, {%0,%1,%2,%3};"
        : "+f"(d[0]), "+f"(d[1]), "+f"(d[2]), "+f"(d[3])
        : "r"(a.x), "r"(a.y), "r"(a.z), "r"(a.w), "r"(b.x), "r"(b.y));
}

// NEON/LLVM-emulated sum of squares (frozen: matches reference c_sq / x_sq)
__device__ __forceinline__ float neon_sumsq64(const float* v) {
    float a0[4] = {0.f,0.f,0.f,0.f}, a1[4] = {0.f,0.f,0.f,0.f};
    #pragma unroll
    for (int i = 0; i < 8; ++i) {
        #pragma unroll
        for (int l = 0; l < 4; ++l) {
            a0[l] = __fadd_rn(a0[l], __fmul_rn(v[8*i+l],   v[8*i+l]));
            a1[l] = __fadd_rn(a1[l], __fmul_rn(v[8*i+4+l], v[8*i+4+l]));
        }
    }
    float s0 = __fadd_rn(a0[0],a1[0]), s1 = __fadd_rn(a0[1],a1[1]);
    float s2 = __fadd_rn(a0[2],a1[2]), s3 = __fadd_rn(a0[3],a1[3]);
    return __fadd_rn(__fadd_rn(s0,s1), __fadd_rn(s2,s3));
}

// FROZEN H1 exact dist (bit-identical to reference): dot = rn-mul + rn-add
// chain over d ascending; dist = fl(fl(xsq - fl(2*dot)) + csq).
__device__ __forceinline__ float h1_dist(const float* __restrict__ xg, float xsq,
                                         const float* __restrict__ cg, float csqk) {
    float ea = 0.f;
    #pragma unroll 8
    for (int d = 0; d < 64; ++d)
        ea = __fadd_rn(ea, __fmul_rn(xg[d], cg[d]));
    return __fadd_rn(__fsub_rn(xsq, __fmul_rn(2.0f, ea)), csqk);
}

// running (min, argmin) + second-min value (no index)
__device__ __forceinline__ void upd(float& m1, float& m2, int& i1, float s, int k) {
    if (s < m1) { m2 = m1; m1 = s; i1 = k; }
    else        { m2 = fminf(m2, s); }
}

extern "C" __global__ void __launch_bounds__(THREADS, 2)
pq_mma_kernel(const float* __restrict__ x,
              const float* __restrict__ cb,
              float* __restrict__ qout,
              float* __restrict__ idf,
              long long* __restrict__ idl,
              int id_mode)
{
    extern __shared__ float smem[];
    uint32_t* Af = reinterpret_cast<uint32_t*>(smem + SM_AF);
    uint32_t* Bf = reinterpret_cast<uint32_t*>(smem + SM_BF);
    float*   csq = smem + SM_CSQ;

    const int tid  = threadIdx.x;
    const int w    = tid >> 5;
    const int lane = tid & 31;
    const int g    = lane >> 2;
    const int tq   = lane & 3;
    const int m    = blockIdx.y;
    const int n0   = blockIdx.x * TILE_M;
    const float* cbm = cb + (size_t)m * PQ_K * PQ_D;

    // ---- stage A: tid<128 stages x row tid (verified R9/R10 layout) ----
    if (tid < 128) {
        const int n = n0 + tid;
        const float4* gx = (n < PQ_N)
            ? reinterpret_cast<const float4*>(
                  x + (size_t)n * (PQ_M * PQ_D) + (size_t)m * PQ_D)
            : nullptr;
        const int rt = tid >> 4, gg = tid & 7, h8 = (tid >> 3) & 1;
        #pragma unroll
        for (int s = 0; s < 8; ++s) {
            float4 v0, v1;
            if (gx) { v0 = gx[2*s]; v1 = gx[2*s+1]; }
            else    { v0 = make_float4(0,0,0,0); v1 = v0; }
            uint32_t* base = Af + (((rt*8 + s)*32 + gg*4) << 2);
            base[(0<<2) + 0 + h8] = f2tf32(v0.x);
            base[(1<<2) + 0 + h8] = f2tf32(v0.y);
            base[(2<<2) + 0 + h8] = f2tf32(v0.z);
            base[(3<<2) + 0 + h8] = f2tf32(v0.w);
            base[(0<<2) + 2 + h8] = f2tf32(v1.x);
            base[(1<<2) + 2 + h8] = f2tf32(v1.y);
            base[(2<<2) + 2 + h8] = f2tf32(v1.z);
            base[(3<<2) + 2 + h8] = f2tf32(v1.w);
        }
    }

    // ---- stage B: all 256 threads stage cb row k=tid; exact NEON csq ----
    {
        const int k = tid;
        const float4* src = reinterpret_cast<const float4*>(cbm + (size_t)k * PQ_D);
        const int ct = k >> 3, c = k & 7;
        float a0[4] = {0,0,0,0}, a1[4] = {0,0,0,0};
        #pragma unroll
        for (int s = 0; s < 8; ++s) {
            float4 v0 = src[2*s], v1 = src[2*s+1];
            a0[0] = __fadd_rn(a0[0], __fmul_rn(v0.x, v0.x));
            a0[1] = __fadd_rn(a0[1], __fmul_rn(v0.y, v0.y));
            a0[2] = __fadd_rn(a0[2], __fmul_rn(v0.z, v0.z));
            a0[3] = __fadd_rn(a0[3], __fmul_rn(v0.w, v0.w));
            a1[0] = __fadd_rn(a1[0], __fmul_rn(v1.x, v1.x));
            a1[1] = __fadd_rn(a1[1], __fmul_rn(v1.y, v1.y));
            a1[2] = __fadd_rn(a1[2], __fmul_rn(v1.z, v1.z));
            a1[3] = __fadd_rn(a1[3], __fmul_rn(v1.w, v1.w));
            uint32_t* base = Bf + (((ct*8 + s)*32 + c*4) << 1);
            base[(0<<1) + 0] = f2tf32(v0.x);
            base[(1<<1) + 0] = f2tf32(v0.y);
            base[(2<<1) + 0] = f2tf32(v0.z);
            base[(3<<1) + 0] = f2tf32(v0.w);
            base[(0<<1) + 1] = f2tf32(v1.x);
            base[(1<<1) + 1] = f2tf32(v1.y);
            base[(2<<1) + 1] = f2tf32(v1.z);
            base[(3<<1) + 1] = f2tf32(v1.w);
        }
        float s0 = __fadd_rn(a0[0],a1[0]), s1 = __fadd_rn(a0[1],a1[1]);
        float s2 = __fadd_rn(a0[2],a1[2]), s3 = __fadd_rn(a0[3],a1[3]);
        csq[k] = __fadd_rn(__fadd_rn(s0,s1), __fadd_rn(s2,s3));
    }
    __syncthreads();

    // ---- preload this warp's A fragments (row-tile = w): 32 regs ----
    const uint4* Af4 = reinterpret_cast<const uint4*>(Af);
    const uint2* Bf2 = reinterpret_cast<const uint2*>(Bf);
    uint4 afr[8];
    #pragma unroll
    for (int s = 0; s < 8; ++s) afr[s] = Af4[(w*8 + s)*32 + lane];

    // per-row state: 2 rows/thread (a: row w*16+g, b: row w*16+8+g)
    float m1a = FLT_BIG, m2a = FLT_BIG, m1b = FLT_BIG, m2b = FLT_BIG;
    int   i1a = 0, i1b = 0;

    // ---- main: 8 groups of 4 col-tiles (4 independent mma chains) ----
    #pragma unroll 1
    for (int ctl = 0; ctl < 32; ctl += 4) {
        float acc[4][4];
        #pragma unroll
        for (int c = 0; c < 4; ++c)
            #pragma unroll
            for (int q = 0; q < 4; ++q) acc[c][q] = 0.f;

        #pragma unroll
        for (int s = 0; s < 8; ++s) {
            const uint2* bp = &Bf2[(ctl*8 + s)*32 + lane];
            uint2 b0 = bp[0*8*32];
            uint2 b1 = bp[1*8*32];
            uint2 b2 = bp[2*8*32];
            uint2 b3 = bp[3*8*32];
            mma8(acc[0], afr[s], b0);
            mma8(acc[1], afr[s], b1);
            mma8(acc[2], afr[s], b2);
            mma8(acc[3], afr[s], b3);
        }

        // scores s = csq[k] - 2*cross (exact csq, tf32 cross); ascending k
        #pragma unroll
        for (int c = 0; c < 4; ++c) {
            const int k0 = (ctl + c)*8 + tq*2;
            upd(m1a, m2a, i1a, fmaf(-2.0f, acc[c][0], csq[k0    ]), k0);
            upd(m1a, m2a, i1a, fmaf(-2.0f, acc[c][1], csq[k0 + 1]), k0 + 1);
            upd(m1b, m2b, i1b, fmaf(-2.0f, acc[c][2], csq[k0    ]), k0);
            upd(m1b, m2b, i1b, fmaf(-2.0f, acc[c][3], csq[k0 + 1]), k0 + 1);
        }
    }

    // ---- finalize 2 rows (verified R10 logic, unconditional shfls) ----
    #pragma unroll 1
    for (int ri = 0; ri < 2; ++ri) {
        const float m1 = ri ? m1b : m1a;
        const float m2 = ri ? m2b : m2a;
        const int   i1 = ri ? i1b : i1a;
        const int  row = w*16 + ri*8 + g;
        const int    n = n0 + row;

        // quad reduce approx min (tie -> lower k)
        float gm = m1; int gk = i1;
        #pragma unroll
        for (int off = 1; off <= 2; off <<= 1) {
            float om = __shfl_xor_sync(0xffffffffu, gm, off);
            int   ok = __shfl_xor_sync(0xffffffffu, gk, off);
            if (om < gm || (om == gm && ok < gk)) { gm = om; gk = ok; }
        }
        const float thr = gm + WINDOW;

        int nv = (m1 < thr);
        nv += __shfl_xor_sync(0xffffffffu, nv, 1);
        nv += __shfl_xor_sync(0xffffffffu, nv, 2);
        int o = (m2 < thr);
        o |= __shfl_xor_sync(0xffffffffu, o, 1);
        o |= __shfl_xor_sync(0xffffffffu, o, 2);

        const bool need = (nv >= 2) || o;
        const bool refine = (n < PQ_N) && need;

        float bd = FLT_BIG; int bk = 1 << 30;
        if (refine) {
            const float* xg = x + (size_t)n * (PQ_M * PQ_D) + (size_t)m * PQ_D;
            const float xsq = neon_sumsq64(xg);
            if (m2 < thr) {
                // hidden candidates possible: exact scan this thread's 64 ks
                for (int ct = 0; ct < 32; ++ct) {
                    #pragma unroll
                    for (int j = 0; j < 2; ++j) {
                        const int k = ct*8 + tq*2 + j;
                        float dd = h1_dist(xg, xsq, cbm + (size_t)k * PQ_D, csq[k]);
                        if (dd < bd || (dd == bd && k < bk)) { bd = dd; bk = k; }
                    }
                }
            } else if (m1 < thr) {
                bd = h1_dist(xg, xsq, cbm + (size_t)i1 * PQ_D, csq[i1]);
                bk = i1;
            }
        }
        // quad reduce exact best (tie -> lower k)
        #pragma unroll
        for (int off = 1; off <= 2; off <<= 1) {
            float ob = __shfl_xor_sync(0xffffffffu, bd, off);
            int   ok = __shfl_xor_sync(0xffffffffu, bk, off);
            if (ob < bd || (ob == bd && ok < bk)) { bd = ob; bk = ok; }
        }

        const int ibest = need ? bk : gk;

        if (n < PQ_N && tq == 0) {
            const float4* cg4 = reinterpret_cast<const float4*>(
                cbm + (size_t)ibest * PQ_D);
            float4* qrow = reinterpret_cast<float4*>(
                qout + (size_t)n * (PQ_M * PQ_D) + (size_t)m * PQ_D);
            #pragma unroll
            for (int d4 = 0; d4 < 16; ++d4) qrow[d4] = cg4[d4];
            if (id_mode == 1)      idf[(size_t)m * PQ_N + n] = (float)ibest;
            else if (id_mode == 2) idl[(size_t)m * PQ_N + n] = (long long)ibest;
        }
    }
}

extern "C" void kernel_launch(void* const* d_in, const int* in_sizes, int n_in,
                              void* d_out, int out_size) {
    const float* x  = (const float*)d_in[0];   // (N, 512) f32
    const float* cb = (const float*)d_in[1];   // (8, 256, 64) f32

    float* out = (float*)d_out;
    const long long QN  = (long long)PQ_N * PQ_M * PQ_D;  // 51,200,000
    const long long IDN = (long long)PQ_M * PQ_N;         // 800,000

    int id_mode = 0;
    float* idf = nullptr;
    long long* idl = nullptr;
    long long osz = (long long)out_size;
    if (osz >= QN + 2 * IDN) {
        id_mode = 2;
        idl = reinterpret_cast<long long*>(out + QN);
    } else if (osz >= QN + IDN) {
        id_mode = 1;
        idf = out + QN;
    }

    const int smem_bytes = SM_FLOATS * sizeof(float);  // ~97KB
    cudaFuncSetAttribute(pq_mma_kernel,
                         cudaFuncAttributeMaxDynamicSharedMemorySize, smem_bytes);

    dim3 grid((PQ_N + TILE_M - 1) / TILE_M, PQ_M);
    pq_mma_kernel<<<grid, THREADS, smem_bytes>>>(x, cb, out, idf, idl, id_mode);
}

// round 12
// speedup vs baseline: 3.4623x; 2.0784x over previous
#include <cuda_runtime.h>
#include <cuda_bf16.h>
#include <cstdint>

// Problem constants (fixed by the reference): N=100000, M=8, K=256, D=64
#define PQ_N 100000
#define PQ_M 8
#define PQ_K 256
#define PQ_D 64
#define THREADS 256
#define ROWS_PB 64              // rows per block (8 per warp)
#define FLT_BIG 3.402823466e38f

// smem (floats):
//   cs   [64][256]  transposed codebook cs[d][k]        16384
//   xs   [64][64]   transposed x tile, PRE-NEGATED      4096
//   csq  [256]      ||c_k||^2 (NEON order)              256
//   scsq [256]      0.5*||c_k||^2 (acc init)            256
//   xsqs [64]       ||x_n||^2 (NEON order)              64
#define SM_CS   0
#define SM_XS   16384
#define SM_CSQ  (SM_XS + 4096)
#define SM_SCSQ (SM_CSQ + 256)
#define SM_XSQ  (SM_SCSQ + 256)
#define SM_FLOATS (SM_XSQ + 64)

// ---------------- packed f32x2 helpers ----------------
__device__ __forceinline__ unsigned long long pack2(float a) {
    unsigned long long r;
    asm("mov.b64 %0, {%1, %1};" : "=l"(r) : "f"(a));
    return r;
}
__device__ __forceinline__ void ffma2(unsigned long long &d,
                                      unsigned long long a,
                                      unsigned long long b) {
    asm("fma.rn.f32x2 %0, %1, %2, %0;" : "+l"(d) : "l"(a), "l"(b));
}
__device__ __forceinline__ float2 unpack2(unsigned long long v) {
    float2 f;
    asm("mov.b64 {%0, %1}, %2;" : "=f"(f.x), "=f"(f.y) : "l"(v));
    return f;
}

// NEON/LLVM-emulated sum of squares (frozen: matches reference c_sq / x_sq)
__device__ __forceinline__ float neon_sumsq64(const float* v) {
    float a0[4] = {0.f,0.f,0.f,0.f}, a1[4] = {0.f,0.f,0.f,0.f};
    #pragma unroll
    for (int i = 0; i < 8; ++i) {
        #pragma unroll
        for (int l = 0; l < 4; ++l) {
            a0[l] = __fadd_rn(a0[l], __fmul_rn(v[8*i+l],   v[8*i+l]));
            a1[l] = __fadd_rn(a1[l], __fmul_rn(v[8*i+4+l], v[8*i+4+l]));
        }
    }
    float s0 = __fadd_rn(a0[0],a1[0]), s1 = __fadd_rn(a0[1],a1[1]);
    float s2 = __fadd_rn(a0[2],a1[2]), s3 = __fadd_rn(a0[3],a1[3]);
    return __fadd_rn(__fadd_rn(s0,s1), __fadd_rn(s2,s3));
}

extern "C" __global__ void __launch_bounds__(THREADS, 2)
pq_lanek_kernel(const float* __restrict__ x,
                const float* __restrict__ cb,
                float* __restrict__ qout,
                float* __restrict__ idf,
                long long* __restrict__ idl,
                int id_mode)
{
    extern __shared__ float smem[];
    float* cs   = smem + SM_CS;
    float* xs   = smem + SM_XS;
    float* csq  = smem + SM_CSQ;
    float* scsq = smem + SM_SCSQ;
    float* xsqs = smem + SM_XSQ;

    const int tid  = threadIdx.x;
    const int w    = tid >> 5;
    const int lane = tid & 31;
    const int m    = blockIdx.y;
    const int n0   = blockIdx.x * ROWS_PB;
    const float* cbm = cb + (size_t)m * PQ_K * PQ_D;

    // ---- stage codebook row k=tid (transposed); NEON csq; 0.5*csq ----
    {
        const float4* src = reinterpret_cast<const float4*>(cbm + (size_t)tid * PQ_D);
        float cw[64];
        #pragma unroll
        for (int d4 = 0; d4 < 16; ++d4) {
            float4 v = src[d4];
            int d = d4 * 4;
            cw[d+0]=v.x; cw[d+1]=v.y; cw[d+2]=v.z; cw[d+3]=v.w;
            cs[(d+0)*256 + tid] = v.x;
            cs[(d+1)*256 + tid] = v.y;
            cs[(d+2)*256 + tid] = v.z;
            cs[(d+3)*256 + tid] = v.w;
        }
        float sq = neon_sumsq64(cw);
        csq[tid]  = sq;
        scsq[tid] = 0.5f * sq;   // exact power-of-two scale
    }

    // ---- stage x tile: thread (r=tid>>2, q=tid&3) stages 16 dims of row r,
    //      PRE-NEGATED, into xs[d][r] ----
    {
        const int r = tid >> 2, q = tid & 3;
        const int n = n0 + r;
        const float4* gx = reinterpret_cast<const float4*>(
            x + (size_t)n * (PQ_M * PQ_D) + (size_t)m * PQ_D + q * 16);
        #pragma unroll
        for (int i4 = 0; i4 < 4; ++i4) {
            float4 v = (n < PQ_N) ? gx[i4] : make_float4(0,0,0,0);
            const int d0 = q * 16 + i4 * 4;
            xs[(d0+0)*ROWS_PB + r] = -v.x;
            xs[(d0+1)*ROWS_PB + r] = -v.y;
            xs[(d0+2)*ROWS_PB + r] = -v.z;
            xs[(d0+3)*ROWS_PB + r] = -v.w;
        }
    }

    // ---- xsq per row (NEON order, from global; matches reference) ----
    if (tid < ROWS_PB) {
        const int n = n0 + tid;
        float xw[64];
        if (n < PQ_N) {
            const float4* gx = reinterpret_cast<const float4*>(
                x + (size_t)n * (PQ_M * PQ_D) + (size_t)m * PQ_D);
            #pragma unroll
            for (int d4 = 0; d4 < 16; ++d4) {
                float4 v = gx[d4];
                xw[d4*4+0]=v.x; xw[d4*4+1]=v.y; xw[d4*4+2]=v.z; xw[d4*4+3]=v.w;
            }
        } else {
            #pragma unroll
            for (int d = 0; d < 64; ++d) xw[d] = 0.f;
        }
        xsqs[tid] = neon_sumsq64(xw);
    }
    __syncthreads();

    // ---- main: lane owns k-pairs {2*lane + 64j}, warp owns rows w*8..w*8+7.
    // score chain: acc = 0.5*csq + sum_d (-x_d)*c_d, d ascending, fused
    // (bit-identical ordering to the R6-verified fast pass). ----
    const int l2 = 2 * lane;
    unsigned long long acc[4][8];
    #pragma unroll
    for (int j = 0; j < 4; ++j) {
        unsigned long long q0 =
            *reinterpret_cast<const unsigned long long*>(scsq + l2 + 64*j);
        #pragma unroll
        for (int r = 0; r < 8; ++r) acc[j][r] = q0;
    }

    {
        const float* csd = cs + l2;
        const float* xsd = xs + w * 8;
        #pragma unroll 4
        for (int d = 0; d < 64; ++d) {
            unsigned long long c0 = *reinterpret_cast<const unsigned long long*>(csd);
            unsigned long long c1 = *reinterpret_cast<const unsigned long long*>(csd + 64);
            unsigned long long c2 = *reinterpret_cast<const unsigned long long*>(csd + 128);
            unsigned long long c3 = *reinterpret_cast<const unsigned long long*>(csd + 192);
            #pragma unroll
            for (int r = 0; r < 8; ++r) {
                unsigned long long xp = pack2(xsd[r]);   // already -x
                ffma2(acc[0][r], xp, c0);
                ffma2(acc[1][r], xp, c1);
                ffma2(acc[2][r], xp, c2);
                ffma2(acc[3][r], xp, c3);
            }
            csd += 256;
            xsd += ROWS_PB;
        }
    }

    // ---- per-row finalize: butterfly top-2, frozen H1 refine, writes ----
    #pragma unroll 1
    for (int r = 0; r < 8; ++r) {
        // lane-local top2 over its 8 scores, ascending k (strict <)
        float m1 = FLT_BIG, m2 = FLT_BIG;
        int   i1 = 0, i2 = 0;
        #pragma unroll
        for (int j = 0; j < 4; ++j) {
            float2 s = unpack2(acc[j][r]);
            const int k0 = l2 + 64*j;
            if (s.x < m1)      { m2=m1; i2=i1; m1=s.x; i1=k0; }
            else if (s.x < m2) { m2=s.x; i2=k0; }
            if (s.y < m1)      { m2=m1; i2=i1; m1=s.y; i1=k0+1; }
            else if (s.y < m2) { m2=s.y; i2=k0+1; }
        }
        // warp butterfly merge of (m1,i1,m2,i2); ties -> lower k
        #pragma unroll
        for (int off = 1; off < 32; off <<= 1) {
            float o1 = __shfl_xor_sync(0xffffffffu, m1, off);
            int  oi1 = __shfl_xor_sync(0xffffffffu, i1, off);
            float o2 = __shfl_xor_sync(0xffffffffu, m2, off);
            int  oi2 = __shfl_xor_sync(0xffffffffu, i2, off);
            if (o1 < m1 || (o1 == m1 && oi1 < i1)) {
                // other best wins; second = best of {m1, o2}
                if (m1 < o2 || (m1 == o2 && i1 < oi2)) { m2 = m1; i2 = i1; }
                else                                   { m2 = o2; i2 = oi2; }
                m1 = o1; i1 = oi1;
            } else {
                if (o1 < m2 || (o1 == m2 && oi1 < i2)) { m2 = o1; i2 = oi1; }
            }
        }

        const int row = w*8 + r;
        const int n   = n0 + row;
        int ibest = i1;

        // FROZEN H1 refinement (verified exact vs reference): dot = separate
        // rn-mul + rn-add chain over d ascending; dist left-assoc; tie -> lower
        // k. Score-gap 0.75e-3 == dist-gap 1.5e-3 window.
        if (n < PQ_N && (m2 - m1 < 0.75e-3f)) {
            if (lane == 0) {
                const float* xg = x + (size_t)n * (PQ_M * PQ_D) + (size_t)m * PQ_D;
                float ea = 0.f, eb = 0.f;
                #pragma unroll 4
                for (int d = 0; d < 64; ++d) {
                    float xv = xg[d];
                    ea = __fadd_rn(ea, __fmul_rn(xv, cs[d*256 + i1]));
                    eb = __fadd_rn(eb, __fmul_rn(xv, cs[d*256 + i2]));
                }
                const float xsq = xsqs[row];
                float da = __fadd_rn(__fsub_rn(xsq, __fmul_rn(2.0f, ea)), csq[i1]);
                float db = __fadd_rn(__fsub_rn(xsq, __fmul_rn(2.0f, eb)), csq[i2]);
                if (db < da || (db == da && i2 < i1)) ibest = i2;
            }
        }
        ibest = __shfl_sync(0xffffffffu, ibest, 0);

        if (n < PQ_N) {
            if (lane < 16) {
                // Q row: copy selected codeword (global cb is L1/L2-hot)
                float4 v = reinterpret_cast<const float4*>(
                    cbm + (size_t)ibest * PQ_D)[lane];
                reinterpret_cast<float4*>(
                    qout + (size_t)n * (PQ_M * PQ_D) + (size_t)m * PQ_D)[lane] = v;
            }
            if (lane == 0) {
                if (id_mode == 1)      idf[(size_t)m * PQ_N + n] = (float)ibest;
                else if (id_mode == 2) idl[(size_t)m * PQ_N + n] = (long long)ibest;
            }
        }
    }
}

extern "C" void kernel_launch(void* const* d_in, const int* in_sizes, int n_in,
                              void* d_out, int out_size) {
    const float* x  = (const float*)d_in[0];   // (N, 512) f32
    const float* cb = (const float*)d_in[1];   // (8, 256, 64) f32

    float* out = (float*)d_out;
    const long long QN  = (long long)PQ_N * PQ_M * PQ_D;  // 51,200,000
    const long long IDN = (long long)PQ_M * PQ_N;         // 800,000

    int id_mode = 0;
    float* idf = nullptr;
    long long* idl = nullptr;
    long long osz = (long long)out_size;
    if (osz >= QN + 2 * IDN) {
        id_mode = 2;
        idl = reinterpret_cast<long long*>(out + QN);
    } else if (osz >= QN + IDN) {
        id_mode = 1;
        idf = out + QN;
    }

    const int smem_bytes = SM_FLOATS * sizeof(float);  // ~82.3KB
    cudaFuncSetAttribute(pq_lanek_kernel,
                         cudaFuncAttributeMaxDynamicSharedMemorySize, smem_bytes);

    dim3 grid((PQ_N + ROWS_PB - 1) / ROWS_PB, PQ_M);
    pq_lanek_kernel<<<grid, THREADS, smem_bytes>>>(x, cb, out, idf, idl, id_mode);
}

// round 13
// speedup vs baseline: 4.2065x; 1.2150x over previous
#include <cuda_runtime.h>
#include <cuda_bf16.h>
#include <cstdint>

// Problem constants (fixed by the reference): N=100000, M=8, K=256, D=64
#define PQ_N 100000
#define PQ_M 8
#define PQ_K 256
#define PQ_D 64
#define NTILE 512          // n-rows per block
#define THREADS 512        // 16 warps: (w&7) row-block, (w>>3) k-half
#define FLT_BIG 3.402823466e38f

// ---------------- packed f32x2 helpers ----------------
__device__ __forceinline__ unsigned long long pack2(float a) {
    unsigned long long r;
    asm("mov.b64 %0, {%1, %1};" : "=l"(r) : "f"(a));
    return r;
}
__device__ __forceinline__ void ffma2(unsigned long long &d,
                                      unsigned long long a,
                                      unsigned long long b) {
    asm("fma.rn.f32x2 %0, %1, %2, %0;" : "+l"(d) : "l"(a), "l"(b));
}
__device__ __forceinline__ float2 unpack2(unsigned long long v) {
    float2 f;
    asm("mov.b64 {%0, %1}, %2;" : "=f"(f.x), "=f"(f.y) : "l"(v));
    return f;
}

// NEON/LLVM-emulated sum of squares (frozen: matches reference c_sq / x_sq)
__device__ __forceinline__ float neon_sumsq64(const float* v) {
    float a0[4] = {0.f,0.f,0.f,0.f}, a1[4] = {0.f,0.f,0.f,0.f};
    #pragma unroll
    for (int i = 0; i < 8; ++i) {
        #pragma unroll
        for (int l = 0; l < 4; ++l) {
            a0[l] = __fadd_rn(a0[l], __fmul_rn(v[8*i+l],   v[8*i+l]));
            a1[l] = __fadd_rn(a1[l], __fmul_rn(v[8*i+4+l], v[8*i+4+l]));
        }
    }
    float s0 = __fadd_rn(a0[0],a1[0]), s1 = __fadd_rn(a0[1],a1[1]);
    float s2 = __fadd_rn(a0[2],a1[2]), s3 = __fadd_rn(a0[3],a1[3]);
    return __fadd_rn(__fadd_rn(s0,s1), __fadd_rn(s2,s3));
}

// smem layout (floats):
//   cs    [64][256]      transposed codebook                  16384
//   xs    [64][NTILE]    transposed x tile, PRE-NEGATED       32768
//   csq   [256]          ||c_k||^2 (NEON order)                 256
//   scsq  [256]          0.5*||c_k||^2 (acc init)               256
//   xsqs  [NTILE]        ||x_n||^2 (NEON order)                 512
//   mrgf  [2][NTILE][2]  per-half (m1, m2)                     2048
//   mrgi  [2][NTILE][2]  per-half (i1, i2) (as int)            2048
#define SM_CS    0
#define SM_XS    (64 * 256)
#define SM_CSQ   (SM_XS + 64 * NTILE)
#define SM_SCSQ  (SM_CSQ + 256)
#define SM_XSQ   (SM_SCSQ + 256)
#define SM_MRGF  (SM_XSQ + NTILE)
#define SM_MRGI  (SM_MRGF + 2 * NTILE * 2)
#define SM_FLOATS (SM_MRGI + 2 * NTILE * 2)

extern "C" __global__ void __launch_bounds__(THREADS, 1)
pq_ksplit_kernel(const float* __restrict__ x,
                 const float* __restrict__ cb,
                 float* __restrict__ qout,
                 float* __restrict__ idf,
                 long long* __restrict__ idl,
                 int id_mode)
{
    extern __shared__ float smem[];
    float* cs   = smem + SM_CS;
    float* xs   = smem + SM_XS;
    float* csq  = smem + SM_CSQ;
    float* scsq = smem + SM_SCSQ;
    float* xsqs = smem + SM_XSQ;
    float* mrgf = smem + SM_MRGF;
    int*   mrgi = reinterpret_cast<int*>(smem + SM_MRGI);

    const int tid  = threadIdx.x;
    const int w    = tid >> 5;
    const int lane = tid & 31;
    const int m    = blockIdx.y;
    const int n0   = blockIdx.x * NTILE;
    const float* cbm = cb + (size_t)m * PQ_K * PQ_D;

    // ---- stage codebook (tid<256): transposed cs; NEON csq; 0.5*csq ----
    if (tid < 256) {
        const float4* src = reinterpret_cast<const float4*>(cbm + (size_t)tid * PQ_D);
        float cw[64];
        #pragma unroll
        for (int d4 = 0; d4 < 16; ++d4) {
            float4 v = src[d4];
            int d = d4 * 4;
            cw[d+0]=v.x; cw[d+1]=v.y; cw[d+2]=v.z; cw[d+3]=v.w;
            cs[(d+0)*256 + tid] = v.x;
            cs[(d+1)*256 + tid] = v.y;
            cs[(d+2)*256 + tid] = v.z;
            cs[(d+3)*256 + tid] = v.w;
        }
        float sq = neon_sumsq64(cw);
        csq[tid]  = sq;
        scsq[tid] = 0.5f * sq;   // exact power-of-two scale
    }

    // ---- stage x row tid: transposed + PRE-NEGATED; NEON xsq ----
    {
        const int n = n0 + tid;
        float xw[64];
        if (n < PQ_N) {
            const float4* gx = reinterpret_cast<const float4*>(
                x + (size_t)n * (PQ_M * PQ_D) + (size_t)m * PQ_D);
            #pragma unroll
            for (int d4 = 0; d4 < 16; ++d4) {
                float4 v = gx[d4];
                xw[d4*4+0]=v.x; xw[d4*4+1]=v.y; xw[d4*4+2]=v.z; xw[d4*4+3]=v.w;
            }
        } else {
            #pragma unroll
            for (int d = 0; d < 64; ++d) xw[d] = 0.f;
        }
        #pragma unroll
        for (int d = 0; d < 64; ++d) xs[d * NTILE + tid] = -xw[d];
        xsqs[tid] = neon_sumsq64(xw);   // sign-invariant
    }
    __syncthreads();

    // ---- FAST PASS: warp (w&7) owns rows (w&7)*64 + 2*lane + {0,1};
    //      k-half = (w>>3)*128. Chain: acc = 0.5*csq + sum_d (-x_d)*c_d,
    //      d ascending, fused — bit-identical to the R6-verified pass. ----
    const int half  = w >> 3;
    const int kbase = half * 128;
    const int rw    = (w & 7) * 64 + 2 * lane;   // first of this thread's 2 rows

    float m1a = FLT_BIG, m2a = FLT_BIG, m1b = FLT_BIG, m2b = FLT_BIG;
    int   i1a = 0, i2a = 0, i1b = 0, i2b = 0;

    #pragma unroll 1
    for (int kc = 0; kc < 128; kc += 32) {
        unsigned long long accA[16], accB[16];
        const unsigned long long* q0 =
            reinterpret_cast<const unsigned long long*>(scsq + kbase + kc);
        #pragma unroll
        for (int j = 0; j < 16; ++j) { accA[j] = q0[j]; accB[j] = q0[j]; }

        #pragma unroll 4
        for (int d = 0; d < 64; ++d) {
            float2 xv = *reinterpret_cast<const float2*>(xs + d * NTILE + rw);
            unsigned long long xa = pack2(xv.x);   // already -x
            unsigned long long xb = pack2(xv.y);
            const ulonglong2* cp =
                reinterpret_cast<const ulonglong2*>(cs + d * 256 + kbase + kc);
            #pragma unroll
            for (int j = 0; j < 8; ++j) {
                ulonglong2 c2 = cp[j];
                ffma2(accA[2*j],   xa, c2.x);
                ffma2(accA[2*j+1], xa, c2.y);
                ffma2(accB[2*j],   xb, c2.x);
                ffma2(accB[2*j+1], xb, c2.y);
            }
        }

        // running top-2 per row, ascending k (strict <)
        #pragma unroll
        for (int j = 0; j < 16; ++j) {
            const int k0 = kbase + kc + 2*j;
            float2 sA = unpack2(accA[j]);
            if (sA.x < m1a)      { m2a=m1a; i2a=i1a; m1a=sA.x; i1a=k0; }
            else if (sA.x < m2a) { m2a=sA.x; i2a=k0; }
            if (sA.y < m1a)      { m2a=m1a; i2a=i1a; m1a=sA.y; i1a=k0+1; }
            else if (sA.y < m2a) { m2a=sA.y; i2a=k0+1; }
            float2 sB = unpack2(accB[j]);
            if (sB.x < m1b)      { m2b=m1b; i2b=i1b; m1b=sB.x; i1b=k0; }
            else if (sB.x < m2b) { m2b=sB.x; i2b=k0; }
            if (sB.y < m1b)      { m2b=m1b; i2b=i1b; m1b=sB.y; i1b=k0+1; }
            else if (sB.y < m2b) { m2b=sB.y; i2b=k0+1; }
        }
    }

    // ---- publish per-half top-2 ----
    {
        float* pf = mrgf + (half * NTILE + rw) * 2;
        int*   pi = mrgi + (half * NTILE + rw) * 2;
        pf[0] = m1a; pf[1] = m2a; pi[0] = i1a; pi[1] = i2a;
        pf[2] = m1b; pf[3] = m2b; pi[2] = i1b; pi[3] = i2b;
    }
    __syncthreads();

    // ---- merge + frozen H1 refine + write: thread tid owns row tid ----
    {
        const int row = tid;
        const int n   = n0 + row;

        const float a1 = mrgf[(0 * NTILE + row) * 2 + 0];
        const float a2 = mrgf[(0 * NTILE + row) * 2 + 1];
        const int  ia1 = mrgi[(0 * NTILE + row) * 2 + 0];
        const int  ia2 = mrgi[(0 * NTILE + row) * 2 + 1];
        const float b1 = mrgf[(1 * NTILE + row) * 2 + 0];
        const float b2 = mrgf[(1 * NTILE + row) * 2 + 1];
        const int  ib1 = mrgi[(1 * NTILE + row) * 2 + 0];
        const int  ib2 = mrgi[(1 * NTILE + row) * 2 + 1];

        // merge two sorted pairs; all half0 k < half1 k, ties -> half0
        float best, second; int ibest, isec;
        if (b1 < a1) {
            best = b1; ibest = ib1;
            if (b2 < a1) { second = b2; isec = ib2; }
            else         { second = a1; isec = ia1; }  // tie a1==b2 -> a1 (lower k)
        } else {                                        // tie a1==b1 -> a1
            best = a1; ibest = ia1;
            if (a2 <= b1) { second = a2; isec = ia2; }  // tie a2==b1 -> a2 (lower k)
            else          { second = b1; isec = ib1; }
        }

        // FROZEN H1 refinement (verified exact vs reference): dot = separate
        // rn-mul + rn-add chain over d ascending; dist left-assoc; tie ->
        // lower k. Score-gap 0.75e-3 == dist-gap 1.5e-3 window.
        if (n < PQ_N && (second - best < 0.75e-3f)) {
            const float* xg = x + (size_t)n * (PQ_M * PQ_D) + (size_t)m * PQ_D;
            float ea = 0.f, eb = 0.f;
            #pragma unroll 4
            for (int d = 0; d < 64; ++d) {
                float xv = xg[d];
                ea = __fadd_rn(ea, __fmul_rn(xv, cs[d*256 + ibest]));
                eb = __fadd_rn(eb, __fmul_rn(xv, cs[d*256 + isec]));
            }
            const float xsq = xsqs[row];
            float da = __fadd_rn(__fsub_rn(xsq, __fmul_rn(2.0f, ea)), csq[ibest]);
            float db = __fadd_rn(__fsub_rn(xsq, __fmul_rn(2.0f, eb)), csq[isec]);
            if (db < da || (db == da && isec < ibest)) ibest = isec;
        }

        if (n < PQ_N) {
            // write Q row (selected codeword) from transposed cs
            float* qrow = qout + (size_t)n * (PQ_M * PQ_D) + (size_t)m * PQ_D;
            #pragma unroll
            for (int d4 = 0; d4 < 16; ++d4) {
                float4 v;
                v.x = cs[(d4*4 + 0)*256 + ibest];
                v.y = cs[(d4*4 + 1)*256 + ibest];
                v.z = cs[(d4*4 + 2)*256 + ibest];
                v.w = cs[(d4*4 + 3)*256 + ibest];
                reinterpret_cast<float4*>(qrow)[d4] = v;
            }
            if (id_mode == 1)      idf[(size_t)m * PQ_N + n] = (float)ibest;
            else if (id_mode == 2) idl[(size_t)m * PQ_N + n] = (long long)ibest;
        }
    }
}

extern "C" void kernel_launch(void* const* d_in, const int* in_sizes, int n_in,
                              void* d_out, int out_size) {
    const float* x  = (const float*)d_in[0];   // (N, 512) f32
    const float* cb = (const float*)d_in[1];   // (8, 256, 64) f32

    float* out = (float*)d_out;
    const long long QN  = (long long)PQ_N * PQ_M * PQ_D;  // 51,200,000
    const long long IDN = (long long)PQ_M * PQ_N;         // 800,000

    int id_mode = 0;
    float* idf = nullptr;
    long long* idl = nullptr;
    long long osz = (long long)out_size;
    if (osz >= QN + 2 * IDN) {
        id_mode = 2;
        idl = reinterpret_cast<long long*>(out + QN);
    } else if (osz >= QN + IDN) {
        id_mode = 1;
        idf = out + QN;
    }

    const int smem_bytes = SM_FLOATS * sizeof(float);  // ~212KB
    cudaFuncSetAttribute(pq_ksplit_kernel,
                         cudaFuncAttributeMaxDynamicSharedMemorySize, smem_bytes);

    dim3 grid((PQ_N + NTILE - 1) / NTILE, PQ_M);
    pq_ksplit_kernel<<<grid, THREADS, smem_bytes>>>(x, cb, out, idf, idl, id_mode);
}